// round 14
// baseline (speedup 1.0000x reference)
#include <cuda_runtime.h>
#include <cstdint>

// Problem constants (fixed shapes from the reference)
#define BB   2
#define NN   50000
#define FF   16
#define EE   1600000
#define EH   32      // hidden
#define EOUT 30      // second layer out (padded to 32 internally)
#define NOUT 16      // final out per node

__device__ __forceinline__ float sigmoidf_(float x) {          // precise (finalize)
    return __fdividef(1.0f, 1.0f + __expf(-x));
}
__device__ __forceinline__ float sigmoid_fast(float x) {       // tanh-based (edge MLP)
    float t;
    asm("tanh.approx.f32 %0, %1;" : "=f"(t) : "f"(x * 0.5f));
    return fmaf(t, 0.5f, 0.5f);
}

__device__ __forceinline__ unsigned tf32_(float x) {
    unsigned r;
    asm("cvt.rna.tf32.f32 %0, %1;" : "=r"(r) : "f"(x));
    return r;
}

__device__ __forceinline__ void mma_tf32(float c[4], const unsigned a[4],
                                         unsigned b0, unsigned b1) {
    asm("mma.sync.aligned.m16n8k8.row.col.f32.tf32.tf32.f32 "
        "{%0,%1,%2,%3}, {%4,%5,%6,%7}, {%8,%9}, {%0,%1,%2,%3};"
        : "+f"(c[0]), "+f"(c[1]), "+f"(c[2]), "+f"(c[3])
        : "r"(a[0]), "r"(a[1]), "r"(a[2]), "r"(a[3]), "r"(b0), "r"(b1));
}

__device__ __forceinline__ void red_add4(float* p, float a, float b, float c, float d) {
    asm volatile("red.global.add.v4.f32 [%0], {%1,%2,%3,%4};"
                 :: "l"(p), "f"(a), "f"(b), "f"(c), "f"(d) : "memory");
}

// Per-node, per-batch layer-1 partials (scalar fp32), 128B rows:
// g_A[(b*NN+n)*32 + j] = x[b,n] @ W1[0:16, j] + b1[j]
// g_B[(b*NN+n)*32 + j] = x[b,n] @ W1[16:32, j]
__device__ __align__(128) float g_A[BB * NN * EH];   // 12.8 MB
__device__ __align__(128) float g_B[BB * NN * EH];   // 12.8 MB

__global__ void zero_kernel(float4* __restrict__ out, int n4) {
    int i = blockIdx.x * blockDim.x + threadIdx.x;
    if (i < n4) out[i] = make_float4(0.f, 0.f, 0.f, 0.f);
}

// One thread per (node, batch): builds A/B tables.
__global__ __launch_bounds__(128) void node_kernel(
    const float* __restrict__ nf,    // (B, N, F)
    const float* __restrict__ W1,    // (33, 32)
    const float* __restrict__ b1)    // (32)
{
    __shared__ __align__(16) float sW1[32 * 32];
    __shared__ __align__(16) float sb1[32];

    const int t = threadIdx.x;
    for (int i = t; i < 32 * 32; i += 128) sW1[i] = W1[i];
    if (t < 32) sb1[t] = b1[t];
    __syncthreads();

    const int idx = blockIdx.x * 128 + t;          // 0 .. BB*NN-1
    if (idx >= BB * NN) return;

    const float4* xv = (const float4*)(nf + (size_t)idx * FF);
    float x[16];
    #pragma unroll
    for (int q = 0; q < 4; q++) {
        float4 v = xv[q];
        x[4*q+0] = v.x; x[4*q+1] = v.y; x[4*q+2] = v.z; x[4*q+3] = v.w;
    }

    float accA[32], accB[32];
    #pragma unroll
    for (int j = 0; j < 32; j++) { accA[j] = sb1[j]; accB[j] = 0.0f; }
    #pragma unroll
    for (int k = 0; k < 16; k++) {
        const float xa = x[k];
        #pragma unroll
        for (int j = 0; j < 32; j++) {
            accA[j] = fmaf(xa, sW1[k * 32 + j], accA[j]);
            accB[j] = fmaf(xa, sW1[(16 + k) * 32 + j], accB[j]);
        }
    }
    float4* da = (float4*)(g_A + (size_t)idx * EH);
    float4* db = (float4*)(g_B + (size_t)idx * EH);
    #pragma unroll
    for (int q = 0; q < 8; q++) {
        da[q] = make_float4(accA[4*q+0], accA[4*q+1], accA[4*q+2], accA[4*q+3]);
        db[q] = make_float4(accB[4*q+0], accB[4*q+1], accB[4*q+2], accB[4*q+3]);
    }
}

// One thread per (edge, batch); warp-cooperative gather with layer-1 fully fused
// into the staging pass; tf32 mma for L2/L3. Block = 128 threads (4 warps),
// 32 edges per warp.
#define SLOT_F 36    // staging slot stride in floats (144 B); 36 % 32 == 4
__global__ __launch_bounds__(128) void edge_kernel(
    const float* __restrict__ ew,          // (B, E)
    const int*   __restrict__ eidx,        // (2, E) int32 (or int64 -- probed)
    const float* __restrict__ W1,          // (33, 32) -- only row 32 used here
    const float* __restrict__ W2,          // (32, 30)
    const float* __restrict__ b2,          // (30)
    const float* __restrict__ W3,          // (30, 16)
    float* __restrict__ out,               // (B, N, 16) accumulator
    int e0)                                // edge offset of this launch
{
    // Weight fragments, scalar-split (bank = lane -> conflict-free LDS.32):
    __shared__ __align__(16) unsigned sW2x[16 * 32];  // [(k*4+n)][lane] reg b0
    __shared__ __align__(16) unsigned sW2y[16 * 32];  // [(k*4+n)][lane] reg b1
    __shared__ __align__(16) unsigned sW3x[8 * 32];   // [(k*2+n)][lane]
    __shared__ __align__(16) unsigned sW3y[8 * 32];
    __shared__ __align__(16) float sW1L[32];          // W1 row 32 (edge-weight row)
    __shared__ __align__(16) float sb2[32];           // padded zero
    __shared__ __align__(16) unsigned stage[4][32 * SLOT_F];  // per-warp staging
    __shared__ int s_is64;

    const int t = threadIdx.x;
    // W2 fragments for lane (g4,t4): rows {8k+t4, 8k+t4+4}, col 8n+g4 (cols>=30 zero)
    for (int i = t; i < 512; i += 128) {
        const int ln = i & 31, kn = i >> 5;
        const int k = kn >> 2, n = kn & 3;
        const int t4i = ln & 3, g = ln >> 2;
        const int col = 8 * n + g;
        const int r0 = 8 * k + t4i;
        const float v0 = (col < EOUT) ? W2[r0 * EOUT + col] : 0.0f;
        const float v1 = (col < EOUT) ? W2[(r0 + 4) * EOUT + col] : 0.0f;
        sW2x[i] = tf32_(v0);
        sW2y[i] = tf32_(v1);
    }
    // W3 fragments: rows >= 30 zero (k-dim pad)
    for (int i = t; i < 256; i += 128) {
        const int ln = i & 31, kn = i >> 5;
        const int k = kn >> 1, n = kn & 1;
        const int t4i = ln & 3, g = ln >> 2;
        const int col = 8 * n + g;
        const int r0 = 8 * k + t4i, r1 = r0 + 4;
        const float v0 = (r0 < EOUT) ? W3[r0 * 16 + col] : 0.0f;
        const float v1 = (r1 < EOUT) ? W3[r1 * 16 + col] : 0.0f;
        sW3x[i] = tf32_(v0);
        sW3y[i] = tf32_(v1);
    }
    if (t < 32) sW1L[t] = W1[32 * 32 + t];
    if (t < 32) sb2[t] = (t < EOUT) ? b2[t] : 0.0f;
    if (t == 0) {
        // int64 probe: little-endian int64 (<2^31) => odd int32 words are 0.
        s_is64 = (eidx[1] == 0 && eidx[3] == 0 && eidx[5] == 0 && eidx[7] == 0);
    }
    __syncthreads();

    const int wid  = t >> 5;
    const int lane = t & 31;
    const int g4   = lane >> 2;   // groupID (0..7)
    const int t4   = lane & 3;    // thread-in-group
    const int bsw  = g4 & 1;      // row-parity swizzle bit for h2 transpose
    const int e = e0 + blockIdx.x * 128 + t;
    const int b = blockIdx.y;

    int src, tgt;
    if (s_is64) {
        src = eidx[2 * (size_t)e];
        tgt = eidx[2 * ((size_t)EE + e)];
    } else {
        src = eidx[e];
        tgt = eidx[EE + e];
    }

    const float w = __ldg(ew + (size_t)b * EE + e);

    unsigned* bufu = stage[wid];
    const int chunk = lane & 7;   // which 16B chunk of a row
    const int sub   = lane >> 3;  // which of 4 rows this round

    // ---- staging with FUSED layer 1: store tf32(sigmoid(A+B + w*W1L)) ----
    {
        const float* baseA = g_A + (size_t)b * NN * EH;
        const float* baseB = g_B + (size_t)b * NN * EH;
        const float4 w1l = *(const float4*)(sW1L + chunk * 4);  // cols chunk*4..+3
        #pragma unroll
        for (int i = 0; i < 8; i++) {
            const int eo = i * 4 + sub;                       // edge-in-warp
            const int rA = __shfl_sync(0xffffffffu, src, eo);
            const int rB = __shfl_sync(0xffffffffu, tgt, eo);
            const float we = __shfl_sync(0xffffffffu, w, eo);
            float4 va = *(const float4*)(baseA + (size_t)rA * EH + chunk * 4);
            float4 vb = *(const float4*)(baseB + (size_t)rB * EH + chunk * 4);
            uint4 u;
            u.x = tf32_(sigmoid_fast(fmaf(we, w1l.x, va.x + vb.x)));
            u.y = tf32_(sigmoid_fast(fmaf(we, w1l.y, va.y + vb.y)));
            u.z = tf32_(sigmoid_fast(fmaf(we, w1l.z, va.z + vb.z)));
            u.w = tf32_(sigmoid_fast(fmaf(we, w1l.w, va.w + vb.w)));
            *(uint4*)(bufu + eo * SLOT_F + chunk * 4) = u;
        }
        __syncwarp();
    }

    // ---- A-fragment build: pure LDS (conflict-free: word = 4g4+8k+t4) ----
    unsigned a[2][4][4];
    #pragma unroll
    for (int m = 0; m < 2; m++)
        #pragma unroll
        for (int k = 0; k < 4; k++) {
            const int rlo = (16*m + g4) * SLOT_F;
            const int rhi = (16*m + g4 + 8) * SLOT_F;
            a[m][k][0] = bufu[rlo + 8*k + t4];
            a[m][k][1] = bufu[rhi + 8*k + t4];
            a[m][k][2] = bufu[rlo + 8*k + t4 + 4];
            a[m][k][3] = bufu[rhi + 8*k + t4 + 4];
        }
    __syncwarp();   // staged h1 fully consumed; buf free for h2

    // ---- layer 2 on tensor cores, n-split halves (16 accum regs at a time) ----
    // h2 written back with row-parity XOR swizzle (pos = col ^ (row&1)).
    #pragma unroll
    for (int nh = 0; nh < 2; nh++) {
        float c[2][2][4];
        #pragma unroll
        for (int nn = 0; nn < 2; nn++) {
            const int n = 2*nh + nn;
            const float v0 = sb2[8*n + 2*t4];
            const float v1 = sb2[8*n + 2*t4 + 1];
            #pragma unroll
            for (int m = 0; m < 2; m++) {
                c[m][nn][0] = v0; c[m][nn][1] = v1;
                c[m][nn][2] = v0; c[m][nn][3] = v1;
            }
        }
        #pragma unroll
        for (int k = 0; k < 4; k++)
            #pragma unroll
            for (int nn = 0; nn < 2; nn++) {
                const int n = 2*nh + nn;
                const unsigned bx = sW2x[(k * 4 + n) * 32 + lane];
                const unsigned by = sW2y[(k * 4 + n) * 32 + lane];
                #pragma unroll
                for (int m = 0; m < 2; m++)
                    mma_tf32(c[m][nn], a[m][k], bx, by);
            }
        #pragma unroll
        for (int m = 0; m < 2; m++)
            #pragma unroll
            for (int nn = 0; nn < 2; nn++) {
                const int n = 2*nh + nn;
                const int base0 = (16*m + g4) * SLOT_F;
                const int base1 = (16*m + g4 + 8) * SLOT_F;
                const int cc = 8*n + 2*t4;
                bufu[base0 + cc + bsw]   = tf32_(sigmoid_fast(c[m][nn][0]));
                bufu[base0 + cc + 1-bsw] = tf32_(sigmoid_fast(c[m][nn][1]));
                bufu[base1 + cc + bsw]   = tf32_(sigmoid_fast(c[m][nn][2]));
                bufu[base1 + cc + 1-bsw] = tf32_(sigmoid_fast(c[m][nn][3]));
            }
    }
    __syncwarp();

    // ---- reload h2 as A-fragments (swizzled cols: conflict-free) ----
    {
        const int tlo = t4 ^ bsw;
        #pragma unroll
        for (int m = 0; m < 2; m++)
            #pragma unroll
            for (int k = 0; k < 4; k++) {
                const int rlo = (16*m + g4) * SLOT_F;
                const int rhi = (16*m + g4 + 8) * SLOT_F;
                a[m][k][0] = bufu[rlo + 8*k + tlo];
                a[m][k][1] = bufu[rhi + 8*k + tlo];
                a[m][k][2] = bufu[rlo + 8*k + 4 + tlo];
                a[m][k][3] = bufu[rhi + 8*k + 4 + tlo];
            }
    }

    // ---- layer 3 on tensor cores: d = h2 @ W3 (b3 folded in finalize) ----
    float d[2][2][4];
    #pragma unroll
    for (int m = 0; m < 2; m++)
        #pragma unroll
        for (int n = 0; n < 2; n++)
            d[m][n][0] = d[m][n][1] = d[m][n][2] = d[m][n][3] = 0.0f;
    #pragma unroll
    for (int k = 0; k < 4; k++)
        #pragma unroll
        for (int n = 0; n < 2; n++) {
            const unsigned bx = sW3x[(k * 2 + n) * 32 + lane];
            const unsigned by = sW3y[(k * 2 + n) * 32 + lane];
            #pragma unroll
            for (int m = 0; m < 2; m++)
                mma_tf32(d[m][n], a[m][k], bx, by);
        }

    // ---- scatter: regroup pairs into contiguous 16B chunks, red.v4 ----
    #pragma unroll
    for (int i = 0; i < 4; i++) {
        const int m  = i >> 1;
        const int hi = (i & 1) * 2;
        const int row = g4 + 8 * i;          // rows: g4, g4+8, g4+16, g4+24
        const int rsrc = __shfl_sync(0xffffffffu, src, row);
        const int rtgt = __shfl_sync(0xffffffffu, tgt, row);
        const bool ev = (t4 & 1) == 0;
        const float s0 = ev ? d[m][1][hi]     : d[m][0][hi];
        const float s1 = ev ? d[m][1][hi + 1] : d[m][0][hi + 1];
        const float r0 = __shfl_xor_sync(0xffffffffu, s0, 1);
        const float r1 = __shfl_xor_sync(0xffffffffu, s1, 1);
        const float f0 = ev ? d[m][0][hi]     : r0;
        const float f1 = ev ? d[m][0][hi + 1] : r1;
        const float f2 = ev ? r0              : d[m][1][hi];
        const float f3 = ev ? r1              : d[m][1][hi + 1];
        const int off = ev ? (2 * t4) : (6 + 2 * t4);
        float* pt = out + ((size_t)b * NN + rtgt) * NOUT + off;
        float* ps = out + ((size_t)b * NN + rsrc) * NOUT + off;
        red_add4(pt,  f0,  f1,  f2,  f3);
        red_add4(ps, -f0, -f1, -f2, -f3);
    }
}

__global__ void finalize_kernel(float* __restrict__ out,
                                const float* __restrict__ b3, int n) {
    int i = blockIdx.x * blockDim.x + threadIdx.x;
    if (i < n) {
        float v = out[i] + __ldg(b3 + (i & 15));
        out[i] = sigmoidf_(v);
    }
}

extern "C" void kernel_launch(void* const* d_in, const int* in_sizes, int n_in,
                              void* d_out, int out_size) {
    const float* nf   = (const float*)d_in[0];      // node_features (B,N,F)
    const float* ew   = (const float*)d_in[1];      // edge_weight   (B,E)
    const int*   eidx = (const int*)d_in[2];        // edge_index    (2,E)
    const float* W1   = (const float*)d_in[3];
    const float* b1   = (const float*)d_in[4];
    const float* W2   = (const float*)d_in[5];
    const float* b2   = (const float*)d_in[6];
    const float* W3   = (const float*)d_in[7];
    const float* b3   = (const float*)d_in[8];
    float* out = (float*)d_out;

    const int total = BB * NN * NOUT;  // 1,600,000 floats
    const int n4 = total / 4;

    zero_kernel<<<(n4 + 255) / 256, 256>>>((float4*)out, n4);
    node_kernel<<<(BB * NN + 127) / 128, 128>>>(nf, W1, b1);

    // Edge work split in two launches (also aligns ncu's -s 5 onto edge_kernel).
    dim3 grid((EE / 2) / 128, BB);   // EE % 256 == 0 -> all warps full
    edge_kernel<<<grid, 128>>>(ew, eidx, W1, W2, b2, W3, out, 0);
    edge_kernel<<<grid, 128>>>(ew, eidx, W1, W2, b2, W3, out, EE / 2);

    finalize_kernel<<<(total + 255) / 256, 256>>>(out, b3, total);
}

// round 15
// speedup vs baseline: 1.2990x; 1.2990x over previous
#include <cuda_runtime.h>
#include <cstdint>

// Problem constants (fixed shapes from the reference)
#define BB   2
#define NN   50000
#define FF   16
#define EE   1600000
#define EH   32      // hidden
#define EOUT 30      // second layer out (padded to 32 internally)
#define NOUT 16      // final out per node

__device__ __forceinline__ float sigmoidf_(float x) {          // precise (finalize)
    return __fdividef(1.0f, 1.0f + __expf(-x));
}
__device__ __forceinline__ float sigmoid_fast(float x) {       // tanh-based (edge MLP)
    float t;
    asm("tanh.approx.f32 %0, %1;" : "=f"(t) : "f"(x * 0.5f));
    return fmaf(t, 0.5f, 0.5f);
}

// pack two fp32 into fp16x2: lower half = lo, upper half = hi
__device__ __forceinline__ unsigned packh2(float lo, float hi) {
    unsigned r;
    asm("cvt.rn.f16x2.f32 %0, %1, %2;" : "=r"(r) : "f"(hi), "f"(lo));
    return r;
}

__device__ __forceinline__ void mma_f16(float c[4], const unsigned a[4],
                                        unsigned b0, unsigned b1) {
    asm("mma.sync.aligned.m16n8k16.row.col.f32.f16.f16.f32 "
        "{%0,%1,%2,%3}, {%4,%5,%6,%7}, {%8,%9}, {%0,%1,%2,%3};"
        : "+f"(c[0]), "+f"(c[1]), "+f"(c[2]), "+f"(c[3])
        : "r"(a[0]), "r"(a[1]), "r"(a[2]), "r"(a[3]), "r"(b0), "r"(b1));
}

__device__ __forceinline__ void red_add4(float* p, float a, float b, float c, float d) {
    asm volatile("red.global.add.v4.f32 [%0], {%1,%2,%3,%4};"
                 :: "l"(p), "f"(a), "f"(b), "f"(c), "f"(d) : "memory");
}

// Per-node, per-batch layer-1 partials (scalar fp32), 128B rows:
// g_A[(b*NN+n)*32 + j] = x[b,n] @ W1[0:16, j] + b1[j]
// g_B[(b*NN+n)*32 + j] = x[b,n] @ W1[16:32, j]
__device__ __align__(128) float g_A[BB * NN * EH];   // 12.8 MB
__device__ __align__(128) float g_B[BB * NN * EH];   // 12.8 MB

__global__ void zero_kernel(float4* __restrict__ out, int n4) {
    int i = blockIdx.x * blockDim.x + threadIdx.x;
    if (i < n4) out[i] = make_float4(0.f, 0.f, 0.f, 0.f);
}

// One thread per (node, batch): builds A/B tables.
__global__ __launch_bounds__(128) void node_kernel(
    const float* __restrict__ nf,    // (B, N, F)
    const float* __restrict__ W1,    // (33, 32)
    const float* __restrict__ b1)    // (32)
{
    __shared__ __align__(16) float sW1[32 * 32];
    __shared__ __align__(16) float sb1[32];

    const int t = threadIdx.x;
    for (int i = t; i < 32 * 32; i += 128) sW1[i] = W1[i];
    if (t < 32) sb1[t] = b1[t];
    __syncthreads();

    const int idx = blockIdx.x * 128 + t;          // 0 .. BB*NN-1
    if (idx >= BB * NN) return;

    const float4* xv = (const float4*)(nf + (size_t)idx * FF);
    float x[16];
    #pragma unroll
    for (int q = 0; q < 4; q++) {
        float4 v = xv[q];
        x[4*q+0] = v.x; x[4*q+1] = v.y; x[4*q+2] = v.z; x[4*q+3] = v.w;
    }

    float accA[32], accB[32];
    #pragma unroll
    for (int j = 0; j < 32; j++) { accA[j] = sb1[j]; accB[j] = 0.0f; }
    #pragma unroll
    for (int k = 0; k < 16; k++) {
        const float xa = x[k];
        #pragma unroll
        for (int j = 0; j < 32; j++) {
            accA[j] = fmaf(xa, sW1[k * 32 + j], accA[j]);
            accB[j] = fmaf(xa, sW1[(16 + k) * 32 + j], accB[j]);
        }
    }
    float4* da = (float4*)(g_A + (size_t)idx * EH);
    float4* db = (float4*)(g_B + (size_t)idx * EH);
    #pragma unroll
    for (int q = 0; q < 8; q++) {
        da[q] = make_float4(accA[4*q+0], accA[4*q+1], accA[4*q+2], accA[4*q+3]);
        db[q] = make_float4(accB[4*q+0], accB[4*q+1], accB[4*q+2], accB[4*q+3]);
    }
}

// One thread per (edge, batch); warp-cooperative gather with layer-1 fused into
// the staging pass (stored as fp16x2); fp16 m16n8k16 mma for L2/L3. The h2
// transpose is a pure register conversion (C-frag col pairs == A-frag col pairs).
// Block = 128 threads (4 warps), 32 edges per warp.
#define ROWW 20      // staged h1 row stride in 32-bit words (16 data + 4 pad)
__global__ __launch_bounds__(128) void edge_kernel(
    const float* __restrict__ ew,          // (B, E)
    const int*   __restrict__ eidx,        // (2, E) int32 (or int64 -- probed)
    const float* __restrict__ W1,          // (33, 32) -- only row 32 used here
    const float* __restrict__ W2,          // (32, 30)
    const float* __restrict__ b2,          // (30)
    const float* __restrict__ W3,          // (30, 16)
    float* __restrict__ out,               // (B, N, 16) accumulator
    int e0)                                // edge offset of this launch
{
    // Weight B-fragments, fp16x2 packed, [combo][lane] (bank = lane, conflict-free):
    __shared__ __align__(16) unsigned sW2x[8 * 32];   // [(kt*4+n)][lane] reg b0
    __shared__ __align__(16) unsigned sW2y[8 * 32];   // [(kt*4+n)][lane] reg b1
    __shared__ __align__(16) unsigned sW3x[4 * 32];   // [(kt*2+n)][lane]
    __shared__ __align__(16) unsigned sW3y[4 * 32];
    __shared__ __align__(16) float sW1L[32];          // W1 row 32 (edge-weight row)
    __shared__ __align__(16) float sb2[32];           // padded zero
    __shared__ __align__(16) unsigned stage[4][32 * ROWW];  // h1 fp16x2, per warp
    __shared__ int s_is64;

    const int t = threadIdx.x;
    // W2 B-frags: combo (kt,n): b0 rows {16kt+2t4, +1}, b1 rows {16kt+8+2t4, +1},
    // col 8n+g4 (cols >= 30 zero). fp16x2: lower = first row.
    for (int i = t; i < 256; i += 128) {
        const int ln = i & 31, kn = i >> 5;           // kn: kt*4+n
        const int kt = kn >> 2, n = kn & 3;
        const int t4i = ln & 3, g = ln >> 2;
        const int col = 8 * n + g;
        const int rx = 16 * kt + 2 * t4i;
        const int ry = rx + 8;
        const float x0 = (col < EOUT) ? W2[rx * EOUT + col] : 0.0f;
        const float x1 = (col < EOUT) ? W2[(rx + 1) * EOUT + col] : 0.0f;
        const float y0 = (col < EOUT) ? W2[ry * EOUT + col] : 0.0f;
        const float y1 = (col < EOUT) ? W2[(ry + 1) * EOUT + col] : 0.0f;
        sW2x[i] = packh2(x0, x1);
        sW2y[i] = packh2(y0, y1);
    }
    // W3 B-frags: rows >= 30 zero (k-dim pad)
    for (int i = t; i < 128; i += 128) {
        const int ln = i & 31, kn = i >> 5;           // kn: kt*2+n
        const int kt = kn >> 1, n = kn & 1;
        const int t4i = ln & 3, g = ln >> 2;
        const int col = 8 * n + g;
        const int rx = 16 * kt + 2 * t4i;
        const int ry = rx + 8;
        const float x0 = (rx     < EOUT) ? W3[rx * 16 + col] : 0.0f;
        const float x1 = (rx + 1 < EOUT) ? W3[(rx + 1) * 16 + col] : 0.0f;
        const float y0 = (ry     < EOUT) ? W3[ry * 16 + col] : 0.0f;
        const float y1 = (ry + 1 < EOUT) ? W3[(ry + 1) * 16 + col] : 0.0f;
        sW3x[i] = packh2(x0, x1);
        sW3y[i] = packh2(y0, y1);
    }
    if (t < 32) sW1L[t] = W1[32 * 32 + t];
    if (t < 32) sb2[t] = (t < EOUT) ? b2[t] : 0.0f;
    if (t == 0) {
        // int64 probe: little-endian int64 (<2^31) => odd int32 words are 0.
        s_is64 = (eidx[1] == 0 && eidx[3] == 0 && eidx[5] == 0 && eidx[7] == 0);
    }
    __syncthreads();

    const int wid  = t >> 5;
    const int lane = t & 31;
    const int g4   = lane >> 2;   // groupID (0..7)
    const int t4   = lane & 3;    // thread-in-group
    const int e = e0 + blockIdx.x * 128 + t;
    const int b = blockIdx.y;

    int src, tgt;
    if (s_is64) {
        src = eidx[2 * (size_t)e];
        tgt = eidx[2 * ((size_t)EE + e)];
    } else {
        src = eidx[e];
        tgt = eidx[EE + e];
    }

    const float w = __ldg(ew + (size_t)b * EE + e);

    unsigned* bufu = stage[wid];
    const int chunk = lane & 7;   // which 4-col chunk of a row
    const int sub   = lane >> 3;  // which of 4 rows this round

    // ---- staging with FUSED layer 1: store fp16x2(sigmoid(A+B + w*W1L)) ----
    {
        const float* baseA = g_A + (size_t)b * NN * EH;
        const float* baseB = g_B + (size_t)b * NN * EH;
        const float4 w1l = *(const float4*)(sW1L + chunk * 4);  // cols chunk*4..+3
        #pragma unroll
        for (int i = 0; i < 8; i++) {
            const int eo = i * 4 + sub;                       // edge-in-warp
            const int rA = __shfl_sync(0xffffffffu, src, eo);
            const int rB = __shfl_sync(0xffffffffu, tgt, eo);
            const float we = __shfl_sync(0xffffffffu, w, eo);
            float4 va = *(const float4*)(baseA + (size_t)rA * EH + chunk * 4);
            float4 vb = *(const float4*)(baseB + (size_t)rB * EH + chunk * 4);
            const float h0 = sigmoid_fast(fmaf(we, w1l.x, va.x + vb.x));
            const float h1v = sigmoid_fast(fmaf(we, w1l.y, va.y + vb.y));
            const float h2v = sigmoid_fast(fmaf(we, w1l.z, va.z + vb.z));
            const float h3 = sigmoid_fast(fmaf(we, w1l.w, va.w + vb.w));
            uint2 u;
            u.x = packh2(h0, h1v);   // cols 4c, 4c+1
            u.y = packh2(h2v, h3);   // cols 4c+2, 4c+3
            *(uint2*)(bufu + eo * ROWW + chunk * 2) = u;
        }
        __syncwarp();
    }

    // ---- h1 A-fragments: LDS.32 of fp16x2 pairs (banks 20*g4+t4: conflict-free)
    // a[m][kt]: a0=(row 16m+g4, cols 16kt+2t4,+1) a1=(row+8, same)
    //           a2=(row, cols 16kt+8+2t4,+1)      a3=(row+8, same)
    unsigned ah[2][2][4];
    #pragma unroll
    for (int m = 0; m < 2; m++)
        #pragma unroll
        for (int kt = 0; kt < 2; kt++) {
            const int rlo = (16*m + g4) * ROWW;
            const int rhi = rlo + 8 * ROWW;
            ah[m][kt][0] = bufu[rlo + 8*kt + t4];
            ah[m][kt][1] = bufu[rhi + 8*kt + t4];
            ah[m][kt][2] = bufu[rlo + 8*kt + 4 + t4];
            ah[m][kt][3] = bufu[rhi + 8*kt + 4 + t4];
        }

    // ---- layer 2 on tensor cores: c = h1 @ W2 + b2 ----
    float c[2][4][4];
    #pragma unroll
    for (int m = 0; m < 2; m++)
        #pragma unroll
        for (int n = 0; n < 4; n++) {
            const float v0 = sb2[8*n + 2*t4];
            const float v1 = sb2[8*n + 2*t4 + 1];
            c[m][n][0] = v0; c[m][n][1] = v1; c[m][n][2] = v0; c[m][n][3] = v1;
        }
    #pragma unroll
    for (int kt = 0; kt < 2; kt++)
        #pragma unroll
        for (int n = 0; n < 4; n++) {
            const unsigned bx = sW2x[(kt * 4 + n) * 32 + lane];
            const unsigned by = sW2y[(kt * 4 + n) * 32 + lane];
            #pragma unroll
            for (int m = 0; m < 2; m++)
                mma_f16(c[m][n], ah[m][kt], bx, by);
        }

    // ---- h2: sigmoid + C-frag -> A-frag IN REGISTERS ----
    // C n-tile n covers cols 8n+2t4,+1; A kt-tile needs col pairs at 16kt(+8)+2t4.
    // a0 <- n=2kt regs {0,1}; a1 <- n=2kt regs {2,3}; a2/a3 <- n=2kt+1.
    unsigned a2f[2][2][4];
    #pragma unroll
    for (int m = 0; m < 2; m++)
        #pragma unroll
        for (int kt = 0; kt < 2; kt++) {
            a2f[m][kt][0] = packh2(sigmoid_fast(c[m][2*kt][0]),   sigmoid_fast(c[m][2*kt][1]));
            a2f[m][kt][1] = packh2(sigmoid_fast(c[m][2*kt][2]),   sigmoid_fast(c[m][2*kt][3]));
            a2f[m][kt][2] = packh2(sigmoid_fast(c[m][2*kt+1][0]), sigmoid_fast(c[m][2*kt+1][1]));
            a2f[m][kt][3] = packh2(sigmoid_fast(c[m][2*kt+1][2]), sigmoid_fast(c[m][2*kt+1][3]));
        }

    // ---- layer 3 on tensor cores: d = h2 @ W3 (b3 folded in finalize) ----
    float d[2][2][4];
    #pragma unroll
    for (int m = 0; m < 2; m++)
        #pragma unroll
        for (int n = 0; n < 2; n++)
            d[m][n][0] = d[m][n][1] = d[m][n][2] = d[m][n][3] = 0.0f;
    #pragma unroll
    for (int kt = 0; kt < 2; kt++)
        #pragma unroll
        for (int n = 0; n < 2; n++) {
            const unsigned bx = sW3x[(kt * 2 + n) * 32 + lane];
            const unsigned by = sW3y[(kt * 2 + n) * 32 + lane];
            #pragma unroll
            for (int m = 0; m < 2; m++)
                mma_f16(d[m][n], a2f[m][kt], bx, by);
        }

    // ---- scatter: regroup pairs into contiguous 16B chunks, red.v4 ----
    #pragma unroll
    for (int i = 0; i < 4; i++) {
        const int m  = i >> 1;
        const int hi = (i & 1) * 2;
        const int row = g4 + 8 * i;          // rows: g4, g4+8, g4+16, g4+24
        const int rsrc = __shfl_sync(0xffffffffu, src, row);
        const int rtgt = __shfl_sync(0xffffffffu, tgt, row);
        const bool ev = (t4 & 1) == 0;
        const float s0 = ev ? d[m][1][hi]     : d[m][0][hi];
        const float s1 = ev ? d[m][1][hi + 1] : d[m][0][hi + 1];
        const float r0 = __shfl_xor_sync(0xffffffffu, s0, 1);
        const float r1 = __shfl_xor_sync(0xffffffffu, s1, 1);
        const float f0 = ev ? d[m][0][hi]     : r0;
        const float f1 = ev ? d[m][0][hi + 1] : r1;
        const float f2 = ev ? r0              : d[m][1][hi];
        const float f3 = ev ? r1              : d[m][1][hi + 1];
        const int off = ev ? (2 * t4) : (6 + 2 * t4);
        float* pt = out + ((size_t)b * NN + rtgt) * NOUT + off;
        float* ps = out + ((size_t)b * NN + rsrc) * NOUT + off;
        red_add4(pt,  f0,  f1,  f2,  f3);
        red_add4(ps, -f0, -f1, -f2, -f3);
    }
}

__global__ void finalize_kernel(float* __restrict__ out,
                                const float* __restrict__ b3, int n) {
    int i = blockIdx.x * blockDim.x + threadIdx.x;
    if (i < n) {
        float v = out[i] + __ldg(b3 + (i & 15));
        out[i] = sigmoidf_(v);
    }
}

extern "C" void kernel_launch(void* const* d_in, const int* in_sizes, int n_in,
                              void* d_out, int out_size) {
    const float* nf   = (const float*)d_in[0];      // node_features (B,N,F)
    const float* ew   = (const float*)d_in[1];      // edge_weight   (B,E)
    const int*   eidx = (const int*)d_in[2];        // edge_index    (2,E)
    const float* W1   = (const float*)d_in[3];
    const float* b1   = (const float*)d_in[4];
    const float* W2   = (const float*)d_in[5];
    const float* b2   = (const float*)d_in[6];
    const float* W3   = (const float*)d_in[7];
    const float* b3   = (const float*)d_in[8];
    float* out = (float*)d_out;

    const int total = BB * NN * NOUT;  // 1,600,000 floats
    const int n4 = total / 4;

    zero_kernel<<<(n4 + 255) / 256, 256>>>((float4*)out, n4);
    node_kernel<<<(BB * NN + 127) / 128, 128>>>(nf, W1, b1);

    // Edge work split in two launches (also aligns ncu's -s 5 onto edge_kernel).
    dim3 grid((EE / 2) / 128, BB);   // EE % 256 == 0 -> all warps full
    edge_kernel<<<grid, 128>>>(ew, eidx, W1, W2, b2, W3, out, 0);
    edge_kernel<<<grid, 128>>>(ew, eidx, W1, W2, b2, W3, out, EE / 2);

    finalize_kernel<<<(total + 255) / 256, 256>>>(out, b3, total);
}

// round 16
// speedup vs baseline: 1.5659x; 1.2055x over previous
#include <cuda_runtime.h>
#include <cuda_fp16.h>
#include <cstdint>

// Problem constants (fixed shapes from the reference)
#define BB   2
#define NN   50000
#define FF   16
#define EE   1600000
#define EH   32      // hidden
#define EOUT 30      // second layer out (padded to 32 internally)
#define NOUT 16      // final out per node

__device__ __forceinline__ float sigmoidf_(float x) {          // precise (finalize)
    return __fdividef(1.0f, 1.0f + __expf(-x));
}
__device__ __forceinline__ float sigmoid_fast(float x) {       // tanh-based (edge MLP)
    float t;
    asm("tanh.approx.f32 %0, %1;" : "=f"(t) : "f"(x * 0.5f));
    return fmaf(t, 0.5f, 0.5f);
}

// pack two fp32 into fp16x2: lower half = lo, upper half = hi
__device__ __forceinline__ unsigned packh2(float lo, float hi) {
    unsigned r;
    asm("cvt.rn.f16x2.f32 %0, %1, %2;" : "=r"(r) : "f"(hi), "f"(lo));
    return r;
}
__device__ __forceinline__ float2 h2f2(unsigned u) {
    __half2 h = *reinterpret_cast<__half2*>(&u);
    return __half22float2(h);
}

__device__ __forceinline__ void mma_f16(float c[4], const unsigned a[4],
                                        unsigned b0, unsigned b1) {
    asm("mma.sync.aligned.m16n8k16.row.col.f32.f16.f16.f32 "
        "{%0,%1,%2,%3}, {%4,%5,%6,%7}, {%8,%9}, {%0,%1,%2,%3};"
        : "+f"(c[0]), "+f"(c[1]), "+f"(c[2]), "+f"(c[3])
        : "r"(a[0]), "r"(a[1]), "r"(a[2]), "r"(a[3]), "r"(b0), "r"(b1));
}

__device__ __forceinline__ void red_add4(float* p, float a, float b, float c, float d) {
    asm volatile("red.global.add.v4.f32 [%0], {%1,%2,%3,%4};"
                 :: "l"(p), "f"(a), "f"(b), "f"(c), "f"(d) : "memory");
}

// Per-node, per-batch layer-1 partials, fp16 FRAGMENT-MAJOR, 64B rows.
// Row layout (16 fp16x2 words): word t4*4+p = cols (8p+2t4, 8p+2t4+1).
// A includes +b1; B is the tgt-half partial.
__device__ __align__(128) unsigned g_Ah[BB * NN * 16];   // 6.4 MB
__device__ __align__(128) unsigned g_Bh[BB * NN * 16];   // 6.4 MB

// One thread per (node, batch): builds tables; also grid-stride zeroes out.
__global__ __launch_bounds__(128) void node_kernel(
    const float* __restrict__ nf,    // (B, N, F)
    const float* __restrict__ W1,    // (33, 32)
    const float* __restrict__ b1,    // (32)
    float4* __restrict__ out4,       // (B*N*16)/4 float4 to zero
    int n4)
{
    __shared__ __align__(16) float sW1[32 * 32];
    __shared__ __align__(16) float sb1[32];

    const int t = threadIdx.x;
    // zero the output accumulator (grid-stride)
    for (int i = blockIdx.x * 128 + t; i < n4; i += gridDim.x * 128)
        out4[i] = make_float4(0.f, 0.f, 0.f, 0.f);

    for (int i = t; i < 32 * 32; i += 128) sW1[i] = W1[i];
    if (t < 32) sb1[t] = b1[t];
    __syncthreads();

    const int idx = blockIdx.x * 128 + t;          // 0 .. BB*NN-1
    if (idx >= BB * NN) return;

    const float4* xv = (const float4*)(nf + (size_t)idx * FF);
    float x[16];
    #pragma unroll
    for (int q = 0; q < 4; q++) {
        float4 v = xv[q];
        x[4*q+0] = v.x; x[4*q+1] = v.y; x[4*q+2] = v.z; x[4*q+3] = v.w;
    }

    float accA[32], accB[32];
    #pragma unroll
    for (int j = 0; j < 32; j++) { accA[j] = sb1[j]; accB[j] = 0.0f; }
    #pragma unroll
    for (int k = 0; k < 16; k++) {
        const float xa = x[k];
        #pragma unroll
        for (int j = 0; j < 32; j++) {
            accA[j] = fmaf(xa, sW1[k * 32 + j], accA[j]);
            accB[j] = fmaf(xa, sW1[(16 + k) * 32 + j], accB[j]);
        }
    }
    // pack fragment-major fp16: word t4*4+p = cols (8p+2t4, 8p+2t4+1)
    uint4* da = (uint4*)(g_Ah + (size_t)idx * 16);
    uint4* db = (uint4*)(g_Bh + (size_t)idx * 16);
    #pragma unroll
    for (int t4i = 0; t4i < 4; t4i++) {
        uint4 ua, ub;
        ua.x = packh2(accA[2*t4i],      accA[2*t4i + 1]);
        ua.y = packh2(accA[8 + 2*t4i],  accA[8 + 2*t4i + 1]);
        ua.z = packh2(accA[16 + 2*t4i], accA[16 + 2*t4i + 1]);
        ua.w = packh2(accA[24 + 2*t4i], accA[24 + 2*t4i + 1]);
        ub.x = packh2(accB[2*t4i],      accB[2*t4i + 1]);
        ub.y = packh2(accB[8 + 2*t4i],  accB[8 + 2*t4i + 1]);
        ub.z = packh2(accB[16 + 2*t4i], accB[16 + 2*t4i + 1]);
        ub.w = packh2(accB[24 + 2*t4i], accB[24 + 2*t4i + 1]);
        da[t4i] = ua;
        db[t4i] = ub;
    }
}

// One thread per (edge, batch); direct fragment-aligned gather (no staging),
// fused layer-1, fp16 m16n8k16 mma for L2/L3, m-split for low registers.
// Block = 128 threads (4 warps), 32 edges per warp.
__global__ __launch_bounds__(128, 9) void edge_kernel(
    const float* __restrict__ ew,          // (B, E)
    const int*   __restrict__ eidx,        // (2, E) int32 (or int64 -- probed)
    const float* __restrict__ W1,          // (33, 32) -- only row 32 used here
    const float* __restrict__ W2,          // (32, 30)
    const float* __restrict__ b2,          // (30)
    const float* __restrict__ W3,          // (30, 16)
    float* __restrict__ out,               // (B, N, 16) accumulator
    int e0)                                // edge offset of this launch
{
    // Weight B-fragments, fp16x2 packed, [combo][lane] (bank = lane, conflict-free):
    __shared__ __align__(16) unsigned sW2x[8 * 32];   // [(kt*4+n)][lane] reg b0
    __shared__ __align__(16) unsigned sW2y[8 * 32];   // [(kt*4+n)][lane] reg b1
    __shared__ __align__(16) unsigned sW3x[4 * 32];   // [(kt*2+n)][lane]
    __shared__ __align__(16) unsigned sW3y[4 * 32];
    __shared__ __align__(16) float sW1Lf[32];         // W1 row 32, fragment-major
    __shared__ __align__(16) float sb2[32];           // padded zero
    __shared__ int s_is64;

    const int t = threadIdx.x;
    // W2 B-frags (as in R15)
    for (int i = t; i < 256; i += 128) {
        const int ln = i & 31, kn = i >> 5;           // kn: kt*4+n
        const int kt = kn >> 2, n = kn & 3;
        const int t4i = ln & 3, g = ln >> 2;
        const int col = 8 * n + g;
        const int rx = 16 * kt + 2 * t4i;
        const int ry = rx + 8;
        const float x0 = (col < EOUT) ? W2[rx * EOUT + col] : 0.0f;
        const float x1 = (col < EOUT) ? W2[(rx + 1) * EOUT + col] : 0.0f;
        const float y0 = (col < EOUT) ? W2[ry * EOUT + col] : 0.0f;
        const float y1 = (col < EOUT) ? W2[(ry + 1) * EOUT + col] : 0.0f;
        sW2x[i] = packh2(x0, x1);
        sW2y[i] = packh2(y0, y1);
    }
    // W3 B-frags: rows >= 30 zero (k-dim pad)
    for (int i = t; i < 128; i += 128) {
        const int ln = i & 31, kn = i >> 5;           // kn: kt*2+n
        const int kt = kn >> 1, n = kn & 1;
        const int t4i = ln & 3, g = ln >> 2;
        const int col = 8 * n + g;
        const int rx = 16 * kt + 2 * t4i;
        const int ry = rx + 8;
        const float x0 = (rx     < EOUT) ? W3[rx * 16 + col] : 0.0f;
        const float x1 = (rx + 1 < EOUT) ? W3[(rx + 1) * 16 + col] : 0.0f;
        const float y0 = (ry     < EOUT) ? W3[ry * 16 + col] : 0.0f;
        const float y1 = (ry + 1 < EOUT) ? W3[(ry + 1) * 16 + col] : 0.0f;
        sW3x[i] = packh2(x0, x1);
        sW3y[i] = packh2(y0, y1);
    }
    if (t < 32) {
        // fragment-major W1 last row: pos = t4*8 + p*2 + r -> col 8p+2t4+r
        const int t4i = t >> 3, p = (t & 7) >> 1, r = t & 1;
        sW1Lf[t] = W1[32 * 32 + (8*p + 2*t4i + r)];
        sb2[t] = (t < EOUT) ? b2[t] : 0.0f;
    }
    if (t == 0) {
        // int64 probe: little-endian int64 (<2^31) => odd int32 words are 0.
        s_is64 = (eidx[1] == 0 && eidx[3] == 0 && eidx[5] == 0 && eidx[7] == 0);
    }
    __syncthreads();

    const int lane = t & 31;
    const int g4   = lane >> 2;   // groupID (0..7)
    const int t4   = lane & 3;    // thread-in-group
    const int e = e0 + blockIdx.x * 128 + t;
    const int b = blockIdx.y;

    int src, tgt;
    if (s_is64) {
        src = eidx[2 * (size_t)e];
        tgt = eidx[2 * ((size_t)EE + e)];
    } else {
        src = eidx[e];
        tgt = eidx[EE + e];
    }

    const float w = __ldg(ew + (size_t)b * EE + e);

    // Lane's W1L values: word p = cols (8p+2t4, 8p+2t4+1)
    float2 wlf[4];
    #pragma unroll
    for (int p = 0; p < 4; p++)
        wlf[p] = *(const float2*)(sW1Lf + t4 * 8 + p * 2);

    const unsigned* baseA = g_Ah + (size_t)b * NN * 16;
    const unsigned* baseB = g_Bh + (size_t)b * NN * 16;

    // Two independent 16-row halves (m = 0,1) -> low live-register peak.
    #pragma unroll 1
    for (int m = 0; m < 2; m++) {
        const int r0 = 16 * m + g4;
        const int r1 = r0 + 8;
        const int sA0 = __shfl_sync(0xffffffffu, src, r0);
        const int sB0 = __shfl_sync(0xffffffffu, tgt, r0);
        const int sA1 = __shfl_sync(0xffffffffu, src, r1);
        const int sB1 = __shfl_sync(0xffffffffu, tgt, r1);
        const float w0 = __shfl_sync(0xffffffffu, w, r0);
        const float w1 = __shfl_sync(0xffffffffu, w, r1);

        // Direct fragment-aligned gathers: one LDG.128 per (row, table).
        const uint4 A0 = *(const uint4*)(baseA + (size_t)sA0 * 16 + t4 * 4);
        const uint4 B0 = *(const uint4*)(baseB + (size_t)sB0 * 16 + t4 * 4);
        const uint4 A1 = *(const uint4*)(baseA + (size_t)sA1 * 16 + t4 * 4);
        const uint4 B1 = *(const uint4*)(baseB + (size_t)sB1 * 16 + t4 * 4);

        // Fused layer 1: h1 = sigmoid(A + B + w * W1L), packed into A-frags.
        // word p -> kt = p>>1; (p&1)==0 -> regs {0,1} (cols 16kt+2t4), else {2,3} (+8).
        unsigned ah[2][4];
        {
            const unsigned aw0[4] = {A0.x, A0.y, A0.z, A0.w};
            const unsigned bw0[4] = {B0.x, B0.y, B0.z, B0.w};
            const unsigned aw1[4] = {A1.x, A1.y, A1.z, A1.w};
            const unsigned bw1[4] = {B1.x, B1.y, B1.z, B1.w};
            #pragma unroll
            for (int p = 0; p < 4; p++) {
                const float2 a0 = h2f2(aw0[p]), b0 = h2f2(bw0[p]);
                const float2 a1 = h2f2(aw1[p]), b1v = h2f2(bw1[p]);
                const unsigned u0 = packh2(
                    sigmoid_fast(fmaf(w0, wlf[p].x, a0.x + b0.x)),
                    sigmoid_fast(fmaf(w0, wlf[p].y, a0.y + b0.y)));
                const unsigned u1 = packh2(
                    sigmoid_fast(fmaf(w1, wlf[p].x, a1.x + b1v.x)),
                    sigmoid_fast(fmaf(w1, wlf[p].y, a1.y + b1v.y)));
                const int kt = p >> 1;
                if ((p & 1) == 0) { ah[kt][0] = u0; ah[kt][1] = u1; }
                else              { ah[kt][2] = u0; ah[kt][3] = u1; }
            }
        }

        // Layer 2: c = h1 @ W2 + b2
        float c[4][4];
        #pragma unroll
        for (int n = 0; n < 4; n++) {
            const float v0 = sb2[8*n + 2*t4];
            const float v1 = sb2[8*n + 2*t4 + 1];
            c[n][0] = v0; c[n][1] = v1; c[n][2] = v0; c[n][3] = v1;
        }
        #pragma unroll
        for (int kt = 0; kt < 2; kt++)
            #pragma unroll
            for (int n = 0; n < 4; n++)
                mma_f16(c[n], ah[kt],
                        sW2x[(kt * 4 + n) * 32 + lane],
                        sW2y[(kt * 4 + n) * 32 + lane]);

        // h2: sigmoid + C-frag -> A-frag in registers
        unsigned a2[2][4];
        #pragma unroll
        for (int kt = 0; kt < 2; kt++) {
            a2[kt][0] = packh2(sigmoid_fast(c[2*kt][0]),   sigmoid_fast(c[2*kt][1]));
            a2[kt][1] = packh2(sigmoid_fast(c[2*kt][2]),   sigmoid_fast(c[2*kt][3]));
            a2[kt][2] = packh2(sigmoid_fast(c[2*kt+1][0]), sigmoid_fast(c[2*kt+1][1]));
            a2[kt][3] = packh2(sigmoid_fast(c[2*kt+1][2]), sigmoid_fast(c[2*kt+1][3]));
        }

        // Layer 3: d = h2 @ W3
        float d[2][4];
        #pragma unroll
        for (int n = 0; n < 2; n++)
            d[n][0] = d[n][1] = d[n][2] = d[n][3] = 0.0f;
        #pragma unroll
        for (int kt = 0; kt < 2; kt++)
            #pragma unroll
            for (int n = 0; n < 2; n++)
                mma_f16(d[n], a2[kt],
                        sW3x[(kt * 2 + n) * 32 + lane],
                        sW3y[(kt * 2 + n) * 32 + lane]);

        // Scatter rows r0 (ii=0) and r1 (ii=1); regroup pairs -> red.v4.
        #pragma unroll
        for (int ii = 0; ii < 2; ii++) {
            const int hi = ii * 2;
            const int rsrc = ii ? sA1 : sA0;
            const int rtgt = ii ? sB1 : sB0;
            const bool ev = (t4 & 1) == 0;
            const float s0 = ev ? d[1][hi]     : d[0][hi];
            const float s1 = ev ? d[1][hi + 1] : d[0][hi + 1];
            const float x0 = __shfl_xor_sync(0xffffffffu, s0, 1);
            const float x1 = __shfl_xor_sync(0xffffffffu, s1, 1);
            const float f0 = ev ? d[0][hi]     : x0;
            const float f1 = ev ? d[0][hi + 1] : x1;
            const float f2 = ev ? x0           : d[1][hi];
            const float f3 = ev ? x1           : d[1][hi + 1];
            const int off = ev ? (2 * t4) : (6 + 2 * t4);
            float* pt = out + ((size_t)b * NN + rtgt) * NOUT + off;
            float* ps = out + ((size_t)b * NN + rsrc) * NOUT + off;
            red_add4(pt,  f0,  f1,  f2,  f3);
            red_add4(ps, -f0, -f1, -f2, -f3);
        }
    }
}

__global__ void finalize_kernel(float* __restrict__ out,
                                const float* __restrict__ b3, int n) {
    int i = blockIdx.x * blockDim.x + threadIdx.x;
    if (i < n) {
        float v = out[i] + __ldg(b3 + (i & 15));
        out[i] = sigmoidf_(v);
    }
}

extern "C" void kernel_launch(void* const* d_in, const int* in_sizes, int n_in,
                              void* d_out, int out_size) {
    const float* nf   = (const float*)d_in[0];      // node_features (B,N,F)
    const float* ew   = (const float*)d_in[1];      // edge_weight   (B,E)
    const int*   eidx = (const int*)d_in[2];        // edge_index    (2,E)
    const float* W1   = (const float*)d_in[3];
    const float* b1   = (const float*)d_in[4];
    const float* W2   = (const float*)d_in[5];
    const float* b2   = (const float*)d_in[6];
    const float* W3   = (const float*)d_in[7];
    const float* b3   = (const float*)d_in[8];
    float* out = (float*)d_out;

    const int total = BB * NN * NOUT;  // 1,600,000 floats
    const int n4 = total / 4;

    node_kernel<<<(BB * NN + 127) / 128, 128>>>(nf, W1, b1, (float4*)out, n4);

    // Edge work split in two launches (also aligns ncu's -s 5 onto edge_kernel).
    dim3 grid((EE / 2) / 128, BB);   // EE % 256 == 0 -> all warps full
    edge_kernel<<<grid, 128>>>(ew, eidx, W1, W2, b2, W3, out, 0);
    edge_kernel<<<grid, 128>>>(ew, eidx, W1, W2, b2, W3, out, EE / 2);

    finalize_kernel<<<(total + 255) / 256, 256>>>(out, b3, total);
}

// round 17
// speedup vs baseline: 1.6006x; 1.0221x over previous
#include <cuda_runtime.h>
#include <cuda_fp16.h>
#include <cstdint>

// Problem constants (fixed shapes from the reference)
#define BB   2
#define NN   50000
#define FF   16
#define EE   1600000
#define EH   32      // hidden
#define EOUT 30      // second layer out (padded to 32 internally)
#define NOUT 16      // final out per node

__device__ __forceinline__ float sigmoidf_(float x) {          // precise (finalize)
    return __fdividef(1.0f, 1.0f + __expf(-x));
}
__device__ __forceinline__ float sigmoid_fast(float x) {       // tanh-based (edge MLP)
    float t;
    asm("tanh.approx.f32 %0, %1;" : "=f"(t) : "f"(x * 0.5f));
    return fmaf(t, 0.5f, 0.5f);
}

// pack two fp32 into fp16x2: lower half = lo, upper half = hi
__device__ __forceinline__ unsigned packh2(float lo, float hi) {
    unsigned r;
    asm("cvt.rn.f16x2.f32 %0, %1, %2;" : "=r"(r) : "f"(hi), "f"(lo));
    return r;
}
__device__ __forceinline__ float2 h2f2(unsigned u) {
    __half2 h = *reinterpret_cast<__half2*>(&u);
    return __half22float2(h);
}

__device__ __forceinline__ void mma_f16(float c[4], const unsigned a[4],
                                        unsigned b0, unsigned b1) {
    asm("mma.sync.aligned.m16n8k16.row.col.f32.f16.f16.f32 "
        "{%0,%1,%2,%3}, {%4,%5,%6,%7}, {%8,%9}, {%0,%1,%2,%3};"
        : "+f"(c[0]), "+f"(c[1]), "+f"(c[2]), "+f"(c[3])
        : "r"(a[0]), "r"(a[1]), "r"(a[2]), "r"(a[3]), "r"(b0), "r"(b1));
}

__device__ __forceinline__ void red_add4(float* p, float a, float b, float c, float d) {
    asm volatile("red.global.add.v4.f32 [%0], {%1,%2,%3,%4};"
                 :: "l"(p), "f"(a), "f"(b), "f"(c), "f"(d) : "memory");
}

// Per-node, per-batch layer-1 partials, fp16 FRAGMENT-MAJOR, 64B rows.
// Row layout (16 fp16x2 words): word t4*4+p = cols (8p+2t4, 8p+2t4+1).
// A includes +b1; B is the tgt-half partial.
__device__ __align__(128) unsigned g_Ah[BB * NN * 16];   // 6.4 MB
__device__ __align__(128) unsigned g_Bh[BB * NN * 16];   // 6.4 MB

// One thread per (node, batch): builds tables; also grid-stride zeroes out.
__global__ __launch_bounds__(128) void node_kernel(
    const float* __restrict__ nf,    // (B, N, F)
    const float* __restrict__ W1,    // (33, 32)
    const float* __restrict__ b1,    // (32)
    float4* __restrict__ out4,       // (B*N*16)/4 float4 to zero
    int n4)
{
    __shared__ __align__(16) float sW1[32 * 32];
    __shared__ __align__(16) float sb1[32];

    const int t = threadIdx.x;
    // zero the output accumulator (grid-stride)
    for (int i = blockIdx.x * 128 + t; i < n4; i += gridDim.x * 128)
        out4[i] = make_float4(0.f, 0.f, 0.f, 0.f);

    for (int i = t; i < 32 * 32; i += 128) sW1[i] = W1[i];
    if (t < 32) sb1[t] = b1[t];
    __syncthreads();

    const int idx = blockIdx.x * 128 + t;          // 0 .. BB*NN-1
    if (idx >= BB * NN) return;

    const float4* xv = (const float4*)(nf + (size_t)idx * FF);
    float x[16];
    #pragma unroll
    for (int q = 0; q < 4; q++) {
        float4 v = xv[q];
        x[4*q+0] = v.x; x[4*q+1] = v.y; x[4*q+2] = v.z; x[4*q+3] = v.w;
    }

    float accA[32], accB[32];
    #pragma unroll
    for (int j = 0; j < 32; j++) { accA[j] = sb1[j]; accB[j] = 0.0f; }
    #pragma unroll
    for (int k = 0; k < 16; k++) {
        const float xa = x[k];
        #pragma unroll
        for (int j = 0; j < 32; j++) {
            accA[j] = fmaf(xa, sW1[k * 32 + j], accA[j]);
            accB[j] = fmaf(xa, sW1[(16 + k) * 32 + j], accB[j]);
        }
    }
    // pack fragment-major fp16: word t4*4+p = cols (8p+2t4, 8p+2t4+1)
    uint4* da = (uint4*)(g_Ah + (size_t)idx * 16);
    uint4* db = (uint4*)(g_Bh + (size_t)idx * 16);
    #pragma unroll
    for (int t4i = 0; t4i < 4; t4i++) {
        uint4 ua, ub;
        ua.x = packh2(accA[2*t4i],      accA[2*t4i + 1]);
        ua.y = packh2(accA[8 + 2*t4i],  accA[8 + 2*t4i + 1]);
        ua.z = packh2(accA[16 + 2*t4i], accA[16 + 2*t4i + 1]);
        ua.w = packh2(accA[24 + 2*t4i], accA[24 + 2*t4i + 1]);
        ub.x = packh2(accB[2*t4i],      accB[2*t4i + 1]);
        ub.y = packh2(accB[8 + 2*t4i],  accB[8 + 2*t4i + 1]);
        ub.z = packh2(accB[16 + 2*t4i], accB[16 + 2*t4i + 1]);
        ub.w = packh2(accB[24 + 2*t4i], accB[24 + 2*t4i + 1]);
        da[t4i] = ua;
        db[t4i] = ub;
    }
}

// One thread per (edge, batch); direct fragment-aligned gather (no staging),
// fused layer-1, fp16 m16n8k16 mma for L2/L3, m-split for low registers.
// Block = 128 threads (4 warps), 32 edges per warp. Single launch, full grid.
__global__ __launch_bounds__(128, 8) void edge_kernel(
    const float* __restrict__ ew,          // (B, E)
    const int*   __restrict__ eidx,        // (2, E) int32 (or int64 -- probed)
    const float* __restrict__ W1,          // (33, 32) -- only row 32 used here
    const float* __restrict__ W2,          // (32, 30)
    const float* __restrict__ b2,          // (30)
    const float* __restrict__ W3,          // (30, 16)
    float* __restrict__ out)               // (B, N, 16) accumulator
{
    // Weight B-fragments, fp16x2 packed, [combo][lane] (bank = lane, conflict-free):
    __shared__ __align__(16) unsigned sW2x[8 * 32];   // [(kt*4+n)][lane] reg b0
    __shared__ __align__(16) unsigned sW2y[8 * 32];   // [(kt*4+n)][lane] reg b1
    __shared__ __align__(16) unsigned sW3x[4 * 32];   // [(kt*2+n)][lane]
    __shared__ __align__(16) unsigned sW3y[4 * 32];
    __shared__ __align__(16) float sW1Lf[32];         // W1 row 32, fragment-major
    __shared__ __align__(16) float sb2[32];           // padded zero
    __shared__ int s_is64;

    const int t = threadIdx.x;
    // W2 B-frags
    for (int i = t; i < 256; i += 128) {
        const int ln = i & 31, kn = i >> 5;           // kn: kt*4+n
        const int kt = kn >> 2, n = kn & 3;
        const int t4i = ln & 3, g = ln >> 2;
        const int col = 8 * n + g;
        const int rx = 16 * kt + 2 * t4i;
        const int ry = rx + 8;
        const float x0 = (col < EOUT) ? W2[rx * EOUT + col] : 0.0f;
        const float x1 = (col < EOUT) ? W2[(rx + 1) * EOUT + col] : 0.0f;
        const float y0 = (col < EOUT) ? W2[ry * EOUT + col] : 0.0f;
        const float y1 = (col < EOUT) ? W2[(ry + 1) * EOUT + col] : 0.0f;
        sW2x[i] = packh2(x0, x1);
        sW2y[i] = packh2(y0, y1);
    }
    // W3 B-frags: rows >= 30 zero (k-dim pad)
    for (int i = t; i < 128; i += 128) {
        const int ln = i & 31, kn = i >> 5;           // kn: kt*2+n
        const int kt = kn >> 1, n = kn & 1;
        const int t4i = ln & 3, g = ln >> 2;
        const int col = 8 * n + g;
        const int rx = 16 * kt + 2 * t4i;
        const int ry = rx + 8;
        const float x0 = (rx     < EOUT) ? W3[rx * 16 + col] : 0.0f;
        const float x1 = (rx + 1 < EOUT) ? W3[(rx + 1) * 16 + col] : 0.0f;
        const float y0 = (ry     < EOUT) ? W3[ry * 16 + col] : 0.0f;
        const float y1 = (ry + 1 < EOUT) ? W3[(ry + 1) * 16 + col] : 0.0f;
        sW3x[i] = packh2(x0, x1);
        sW3y[i] = packh2(y0, y1);
    }
    if (t < 32) {
        // fragment-major W1 last row: pos = t4*8 + p*2 + r -> col 8p+2t4+r
        const int t4i = t >> 3, p = (t & 7) >> 1, r = t & 1;
        sW1Lf[t] = W1[32 * 32 + (8*p + 2*t4i + r)];
        sb2[t] = (t < EOUT) ? b2[t] : 0.0f;
    }
    if (t == 0) {
        // int64 probe: little-endian int64 (<2^31) => odd int32 words are 0.
        s_is64 = (eidx[1] == 0 && eidx[3] == 0 && eidx[5] == 0 && eidx[7] == 0);
    }
    __syncthreads();

    const int lane = t & 31;
    const int g4   = lane >> 2;   // groupID (0..7)
    const int t4   = lane & 3;    // thread-in-group
    const int e = blockIdx.x * 128 + t;
    const int b = blockIdx.y;

    int src, tgt;
    if (s_is64) {
        src = eidx[2 * (size_t)e];
        tgt = eidx[2 * ((size_t)EE + e)];
    } else {
        src = eidx[e];
        tgt = eidx[EE + e];
    }

    const float w = __ldg(ew + (size_t)b * EE + e);

    // Lane's W1L values: word p = cols (8p+2t4, 8p+2t4+1)
    float2 wlf[4];
    #pragma unroll
    for (int p = 0; p < 4; p++)
        wlf[p] = *(const float2*)(sW1Lf + t4 * 8 + p * 2);

    // Hoist W3 fragments into registers (8 regs; loaded once, used both m-halves)
    unsigned w3fx[4], w3fy[4];
    #pragma unroll
    for (int cmb = 0; cmb < 4; cmb++) {
        w3fx[cmb] = sW3x[cmb * 32 + lane];
        w3fy[cmb] = sW3y[cmb * 32 + lane];
    }

    const unsigned* baseA = g_Ah + (size_t)b * NN * 16;
    const unsigned* baseB = g_Bh + (size_t)b * NN * 16;

    // Two independent 16-row halves (m = 0,1) -> low live-register peak.
    #pragma unroll 1
    for (int m = 0; m < 2; m++) {
        const int r0 = 16 * m + g4;
        const int r1 = r0 + 8;
        const int sA0 = __shfl_sync(0xffffffffu, src, r0);
        const int sB0 = __shfl_sync(0xffffffffu, tgt, r0);
        const int sA1 = __shfl_sync(0xffffffffu, src, r1);
        const int sB1 = __shfl_sync(0xffffffffu, tgt, r1);
        const float w0 = __shfl_sync(0xffffffffu, w, r0);
        const float w1 = __shfl_sync(0xffffffffu, w, r1);

        // Direct fragment-aligned gathers: one LDG.128 per (row, table).
        const uint4 A0 = *(const uint4*)(baseA + (size_t)sA0 * 16 + t4 * 4);
        const uint4 B0 = *(const uint4*)(baseB + (size_t)sB0 * 16 + t4 * 4);
        const uint4 A1 = *(const uint4*)(baseA + (size_t)sA1 * 16 + t4 * 4);
        const uint4 B1 = *(const uint4*)(baseB + (size_t)sB1 * 16 + t4 * 4);

        // Fused layer 1: h1 = sigmoid(A + B + w * W1L), packed into A-frags.
        // word p -> kt = p>>1; (p&1)==0 -> regs {0,1} (cols 16kt+2t4), else {2,3} (+8).
        unsigned ah[2][4];
        {
            const unsigned aw0[4] = {A0.x, A0.y, A0.z, A0.w};
            const unsigned bw0[4] = {B0.x, B0.y, B0.z, B0.w};
            const unsigned aw1[4] = {A1.x, A1.y, A1.z, A1.w};
            const unsigned bw1[4] = {B1.x, B1.y, B1.z, B1.w};
            #pragma unroll
            for (int p = 0; p < 4; p++) {
                const float2 a0 = h2f2(aw0[p]), b0 = h2f2(bw0[p]);
                const float2 a1 = h2f2(aw1[p]), b1v = h2f2(bw1[p]);
                const unsigned u0 = packh2(
                    sigmoid_fast(fmaf(w0, wlf[p].x, a0.x + b0.x)),
                    sigmoid_fast(fmaf(w0, wlf[p].y, a0.y + b0.y)));
                const unsigned u1 = packh2(
                    sigmoid_fast(fmaf(w1, wlf[p].x, a1.x + b1v.x)),
                    sigmoid_fast(fmaf(w1, wlf[p].y, a1.y + b1v.y)));
                const int kt = p >> 1;
                if ((p & 1) == 0) { ah[kt][0] = u0; ah[kt][1] = u1; }
                else              { ah[kt][2] = u0; ah[kt][3] = u1; }
            }
        }

        // Layer 2: c = h1 @ W2 + b2
        float c[4][4];
        #pragma unroll
        for (int n = 0; n < 4; n++) {
            const float v0 = sb2[8*n + 2*t4];
            const float v1 = sb2[8*n + 2*t4 + 1];
            c[n][0] = v0; c[n][1] = v1; c[n][2] = v0; c[n][3] = v1;
        }
        #pragma unroll
        for (int kt = 0; kt < 2; kt++)
            #pragma unroll
            for (int n = 0; n < 4; n++)
                mma_f16(c[n], ah[kt],
                        sW2x[(kt * 4 + n) * 32 + lane],
                        sW2y[(kt * 4 + n) * 32 + lane]);

        // h2: sigmoid + C-frag -> A-frag in registers
        unsigned a2[2][4];
        #pragma unroll
        for (int kt = 0; kt < 2; kt++) {
            a2[kt][0] = packh2(sigmoid_fast(c[2*kt][0]),   sigmoid_fast(c[2*kt][1]));
            a2[kt][1] = packh2(sigmoid_fast(c[2*kt][2]),   sigmoid_fast(c[2*kt][3]));
            a2[kt][2] = packh2(sigmoid_fast(c[2*kt+1][0]), sigmoid_fast(c[2*kt+1][1]));
            a2[kt][3] = packh2(sigmoid_fast(c[2*kt+1][2]), sigmoid_fast(c[2*kt+1][3]));
        }

        // Layer 3: d = h2 @ W3 (B-frags in registers)
        float d[2][4];
        #pragma unroll
        for (int n = 0; n < 2; n++)
            d[n][0] = d[n][1] = d[n][2] = d[n][3] = 0.0f;
        #pragma unroll
        for (int kt = 0; kt < 2; kt++)
            #pragma unroll
            for (int n = 0; n < 2; n++)
                mma_f16(d[n], a2[kt], w3fx[kt * 2 + n], w3fy[kt * 2 + n]);

        // Scatter rows r0 (ii=0) and r1 (ii=1); regroup pairs -> red.v4.
        #pragma unroll
        for (int ii = 0; ii < 2; ii++) {
            const int hi = ii * 2;
            const int rsrc = ii ? sA1 : sA0;
            const int rtgt = ii ? sB1 : sB0;
            const bool ev = (t4 & 1) == 0;
            const float s0 = ev ? d[1][hi]     : d[0][hi];
            const float s1 = ev ? d[1][hi + 1] : d[0][hi + 1];
            const float x0 = __shfl_xor_sync(0xffffffffu, s0, 1);
            const float x1 = __shfl_xor_sync(0xffffffffu, s1, 1);
            const float f0 = ev ? d[0][hi]     : x0;
            const float f1 = ev ? d[0][hi + 1] : x1;
            const float f2 = ev ? x0           : d[1][hi];
            const float f3 = ev ? x1           : d[1][hi + 1];
            const int off = ev ? (2 * t4) : (6 + 2 * t4);
            float* pt = out + ((size_t)b * NN + rtgt) * NOUT + off;
            float* ps = out + ((size_t)b * NN + rsrc) * NOUT + off;
            red_add4(pt,  f0,  f1,  f2,  f3);
            red_add4(ps, -f0, -f1, -f2, -f3);
        }
    }
}

// Vectorized finalize: one float4 per thread.
__global__ void finalize_kernel(float4* __restrict__ out4,
                                const float4* __restrict__ b3v, int n4) {
    int i = blockIdx.x * blockDim.x + threadIdx.x;
    if (i < n4) {
        const float4 bv = __ldg(b3v + (i & 3));   // 16 floats/row = 4 float4
        float4 v = out4[i];
        v.x = sigmoidf_(v.x + bv.x);
        v.y = sigmoidf_(v.y + bv.y);
        v.z = sigmoidf_(v.z + bv.z);
        v.w = sigmoidf_(v.w + bv.w);
        out4[i] = v;
    }
}

extern "C" void kernel_launch(void* const* d_in, const int* in_sizes, int n_in,
                              void* d_out, int out_size) {
    const float* nf   = (const float*)d_in[0];      // node_features (B,N,F)
    const float* ew   = (const float*)d_in[1];      // edge_weight   (B,E)
    const int*   eidx = (const int*)d_in[2];        // edge_index    (2,E)
    const float* W1   = (const float*)d_in[3];
    const float* b1   = (const float*)d_in[4];
    const float* W2   = (const float*)d_in[5];
    const float* b2   = (const float*)d_in[6];
    const float* W3   = (const float*)d_in[7];
    const float* b3   = (const float*)d_in[8];
    float* out = (float*)d_out;

    const int total = BB * NN * NOUT;  // 1,600,000 floats
    const int n4 = total / 4;

    node_kernel<<<(BB * NN + 127) / 128, 128>>>(nf, W1, b1, (float4*)out, n4);

    dim3 grid(EE / 128, BB);   // EE % 128 == 0 -> all warps full
    edge_kernel<<<grid, 128>>>(ew, eidx, W1, W2, b2, W3, out);

    finalize_kernel<<<(n4 + 255) / 256, 256>>>((float4*)out, (const float4*)b3, n4);
}